// round 13
// baseline (speedup 1.0000x reference)
#include <cuda_runtime.h>
#include <cstdint>
#include <math.h>

#define B_   32
#define N_   3136
#define C_   384
#define H_   8
#define HD_  48
#define NT_  196
#define EPS_ 1e-6f
#define SCALE_ 0.14433756729740643f   /* 1/sqrt(48) */

typedef unsigned long long ull;

// ---------------------------------------------------------------------------
// Scratch: one big static device buffer (no runtime allocation).
// ---------------------------------------------------------------------------
#define XN_OFF   ((size_t)0)
#define KV_OFF   (XN_OFF  + (size_t)B_*N_*C_)
#define QC1_OFF  (KV_OFF  + (size_t)B_*N_*2*C_)
#define HB_OFF   (QC1_OFF + (size_t)B_*NT_*C_)
#define QC2_OFF  (HB_OFF  + (size_t)B_*NT_*2*C_)
#define AV_OFF   (QC2_OFF + (size_t)B_*NT_*C_)
#define CENT_OFF (AV_OFF  + (size_t)B_*NT_*C_)
#define TOTAL_F  (CENT_OFF + (size_t)B_*NT_)

__device__ __align__(128) float g_scratch[TOTAL_F];

#define G_XN   (g_scratch + XN_OFF)
#define G_KV   (g_scratch + KV_OFF)
#define G_QC1  (g_scratch + QC1_OFF)
#define G_HB   (g_scratch + HB_OFF)
#define G_QC2  (g_scratch + QC2_OFF)
#define G_AV   (g_scratch + AV_OFF)
#define G_CENT ((int*)(g_scratch + CENT_OFF))

// ---------------------------------------------------------------------------
// f32x2 packed helpers
// ---------------------------------------------------------------------------
__device__ __forceinline__ ull pack2(float x, float y) {
    ull r; asm("mov.b64 %0, {%1,%2};" : "=l"(r) : "f"(x), "f"(y)); return r;
}
__device__ __forceinline__ float2 unpack2(ull v) {
    float2 f; asm("mov.b64 {%0,%1}, %2;" : "=f"(f.x), "=f"(f.y) : "l"(v)); return f;
}
__device__ __forceinline__ void fma2(ull& d, ull a, ull b) {
    asm("fma.rn.f32x2 %0, %1, %2, %0;" : "+l"(d) : "l"(a), "l"(b));
}

__device__ __forceinline__ float gelu_f(float x) {
    return 0.5f * x * (1.0f + erff(x * 0.70710678118654752f));
}

// ---------------------------------------------------------------------------
// K0: LayerNorm. One block per row, 128 threads, 3 elems/thread.
// ---------------------------------------------------------------------------
__global__ void ln_kernel(const float* __restrict__ x,
                          const float* __restrict__ w,
                          const float* __restrict__ b) {
    int row = blockIdx.x;
    const float* xr = x + (size_t)row * C_;
    int tid = threadIdx.x;
    float v[3];
    float s = 0.f, sq = 0.f;
#pragma unroll
    for (int i = 0; i < 3; i++) {
        v[i] = xr[tid + 128 * i];
        s += v[i]; sq += v[i] * v[i];
    }
#pragma unroll
    for (int o = 16; o; o >>= 1) {
        s  += __shfl_xor_sync(0xffffffffu, s, o);
        sq += __shfl_xor_sync(0xffffffffu, sq, o);
    }
    __shared__ float ss[4], ssq[4];
    if ((tid & 31) == 0) { ss[tid >> 5] = s; ssq[tid >> 5] = sq; }
    __syncthreads();
    s  = ss[0] + ss[1] + ss[2] + ss[3];
    sq = ssq[0] + ssq[1] + ssq[2] + ssq[3];
    float mu = s * (1.0f / C_);
    float var = sq * (1.0f / C_) - mu * mu;
    float rstd = rsqrtf(var + EPS_);
    float* orow = G_XN + (size_t)row * C_;
#pragma unroll
    for (int i = 0; i < 3; i++) {
        int c = tid + 128 * i;
        orow[c] = (v[i] - mu) * rstd * w[c] + b[c];
    }
}

// ---------------------------------------------------------------------------
// GEMM: C[M,Nn] = A[M,K] @ W[Nn,K]^T (+bias)(+gelu)
// NEW (vs R12): block tile 128x64, 8 warps (4m x 2n), thread microtile 8m x 4n,
// acc = 32 regs -> ~70 regs/thread -> __launch_bounds__(256,3): 6 warps/SMSP
// (was 4). LDS latency now hidden; fma pipe becomes the binding pipe.
// Register-staged double-buffered smem, f32x2 math.
// ---------------------------------------------------------------------------
#define BM 128
#define BN 64
#define BK 16

__device__ __forceinline__
void gemm_body(const float* __restrict__ A, const float* __restrict__ W,
               const float* __restrict__ bias, float* __restrict__ Cm,
               int M, int Nn, int K, int epi) {
    __shared__ __align__(16) float As[2][BK][BM];
    __shared__ __align__(16) float Bs[2][BK][BN];
    int tid = threadIdx.x;
    int lane = tid & 31, warp = tid >> 5;
    int m_t = (warp & 3) * 32 + (lane >> 3) * 8;   // thread's 8-row block
    int n_t = (warp >> 2) * 32 + (lane & 7) * 4;   // thread's 4-col block
    int m0 = blockIdx.y * BM, n0 = blockIdx.x * BN;

    // Staging maps: A 128x16 (8 floats/thread), B 64x16 (4 floats/thread)
    int lrA = tid >> 1, lcA = (tid & 1) * 8;
    int lrB = tid >> 2, lcB = (tid & 3) * 4;
    const float* Aptr = A + (size_t)(m0 + lrA) * K + lcA;
    const float* Wptr = W + (size_t)(n0 + lrB) * K + lcB;

    ull acc[8][2];
#pragma unroll
    for (int i = 0; i < 8; i++) { acc[i][0] = 0ull; acc[i][1] = 0ull; }

    float4 a0 = *(const float4*)(Aptr + 0);
    float4 a1 = *(const float4*)(Aptr + 4);
    float4 b0 = *(const float4*)(Wptr + 0);
    As[0][lcA + 0][lrA] = a0.x; As[0][lcA + 1][lrA] = a0.y;
    As[0][lcA + 2][lrA] = a0.z; As[0][lcA + 3][lrA] = a0.w;
    As[0][lcA + 4][lrA] = a1.x; As[0][lcA + 5][lrA] = a1.y;
    As[0][lcA + 6][lrA] = a1.z; As[0][lcA + 7][lrA] = a1.w;
    Bs[0][lcB + 0][lrB] = b0.x; Bs[0][lcB + 1][lrB] = b0.y;
    Bs[0][lcB + 2][lrB] = b0.z; Bs[0][lcB + 3][lrB] = b0.w;
    __syncthreads();

    int nk = K / BK;
    for (int kt = 0; kt < nk; kt++) {
        int cur = kt & 1;
        if (kt + 1 < nk) {
            const float* Ap = Aptr + (kt + 1) * BK;
            const float* Wp = Wptr + (kt + 1) * BK;
            a0 = *(const float4*)(Ap + 0);
            a1 = *(const float4*)(Ap + 4);
            b0 = *(const float4*)(Wp + 0);
        }
#pragma unroll
        for (int kk = 0; kk < BK; kk++) {
            float4 av0 = *(const float4*)&As[cur][kk][m_t];
            float4 av1 = *(const float4*)&As[cur][kk][m_t + 4];
            float4 bv0 = *(const float4*)&Bs[cur][kk][n_t];
            ull bp0 = pack2(bv0.x, bv0.y);
            ull bp1 = pack2(bv0.z, bv0.w);
            float am[8] = {av0.x, av0.y, av0.z, av0.w,
                           av1.x, av1.y, av1.z, av1.w};
#pragma unroll
            for (int i = 0; i < 8; i++) {
                ull ap = pack2(am[i], am[i]);
                fma2(acc[i][0], ap, bp0);
                fma2(acc[i][1], ap, bp1);
            }
        }
        if (kt + 1 < nk) {
            int nxt = 1 - cur;
            As[nxt][lcA + 0][lrA] = a0.x; As[nxt][lcA + 1][lrA] = a0.y;
            As[nxt][lcA + 2][lrA] = a0.z; As[nxt][lcA + 3][lrA] = a0.w;
            As[nxt][lcA + 4][lrA] = a1.x; As[nxt][lcA + 5][lrA] = a1.y;
            As[nxt][lcA + 6][lrA] = a1.z; As[nxt][lcA + 7][lrA] = a1.w;
            Bs[nxt][lcB + 0][lrB] = b0.x; Bs[nxt][lcB + 1][lrB] = b0.y;
            Bs[nxt][lcB + 2][lrB] = b0.z; Bs[nxt][lcB + 3][lrB] = b0.w;
            __syncthreads();
        }
    }

    int gn = n0 + n_t;
    float bb[4];
#pragma unroll
    for (int j = 0; j < 4; j++) bb[j] = bias ? bias[gn + j] : 0.f;
#pragma unroll
    for (int i = 0; i < 8; i++) {
        int gm = m0 + m_t + i;
        float2 c0 = unpack2(acc[i][0]);
        float2 c1 = unpack2(acc[i][1]);
        float o0 = c0.x + bb[0], o1 = c0.y + bb[1];
        float o2 = c1.x + bb[2], o3 = c1.y + bb[3];
        if (epi == 1) {
            o0 = gelu_f(o0); o1 = gelu_f(o1);
            o2 = gelu_f(o2); o3 = gelu_f(o3);
        }
        float4 w0 = {o0, o1, o2, o3};
        *(float4*)(Cm + (size_t)gm * Nn + gn) = w0;
    }
}

__global__ __launch_bounds__(256, 3) void gemm_xn_kv(const float* __restrict__ kv_w) {
    gemm_body(G_XN, kv_w, nullptr, G_KV, B_ * N_, 2 * C_, C_, 0);
}
__global__ __launch_bounds__(256, 3) void gemm_qc1_hb(const float* __restrict__ w,
                                                      const float* __restrict__ b) {
    gemm_body(G_QC1, w, b, G_HB, B_ * NT_, 2 * C_, C_, 1);
}
__global__ __launch_bounds__(256, 3) void gemm_hb_qc2(const float* __restrict__ w,
                                                      const float* __restrict__ b) {
    gemm_body(G_HB, w, b, G_QC2, B_ * NT_, C_, 2 * C_, 0);
}
__global__ __launch_bounds__(256, 3) void gemm_av_out(const float* __restrict__ w,
                                                      const float* __restrict__ b,
                                                      float* __restrict__ out) {
    gemm_body(G_AV, w, b, out, B_ * NT_, C_, C_, 0);
}

// ---------------------------------------------------------------------------
// K2: attn1 + q_cond1. One block per (b,h). (R3-identical.)
// ---------------------------------------------------------------------------
#define ATTN1_SMEM (3 * NT_ * HD_ * 4)

__global__ __launch_bounds__(256)
void attn1_kernel(const float* __restrict__ qg, const int* __restrict__ idx_sub) {
    extern __shared__ float sh[];
    float* qs = sh;
    float* ks = sh + NT_ * HD_;
    float* vs = sh + 2 * NT_ * HD_;
    int b = blockIdx.x >> 3;
    int h = blockIdx.x & 7;
    int tid = threadIdx.x;

    for (int i = tid; i < NT_ * HD_; i += 256) {
        int n = i / HD_, d = i % HD_;
        qs[i] = qg[((size_t)n * H_ + h) * HD_ + d];
        int src = idx_sub[n];
        const float* kvrow = G_KV + ((size_t)b * N_ + src) * (2 * C_) + h * HD_ + d;
        ks[i] = kvrow[0];
        vs[i] = kvrow[C_];
    }
    __syncthreads();

    int m = tid;
    if (m < NT_) {
        float sc[NT_];
        float mx = -1e30f;
        const float* qm = qs + m * HD_;
        for (int n = 0; n < NT_; n++) {
            const float* kn = ks + n * HD_;
            float s = 0.f;
#pragma unroll
            for (int d = 0; d < HD_; d++) s += qm[d] * kn[d];
            s *= SCALE_;
            sc[n] = s;
            mx = fmaxf(mx, s);
        }
        float sum = 0.f;
        for (int n = 0; n < NT_; n++) {
            float e = expf(sc[n] - mx);
            sc[n] = e; sum += e;
        }
        float inv = 1.0f / sum;
        float accv[HD_];
#pragma unroll
        for (int d = 0; d < HD_; d++) accv[d] = 0.f;
        for (int n = 0; n < NT_; n++) {
            float wgt = sc[n];
            const float* vn = vs + n * HD_;
#pragma unroll
            for (int d = 0; d < HD_; d++) accv[d] += wgt * vn[d];
        }
        float* orow = G_QC1 + ((size_t)b * NT_ + m) * C_ + h * HD_;
#pragma unroll
        for (int d = 0; d < HD_; d++) orow[d] = accv[d] * inv;
    }
}

// ---------------------------------------------------------------------------
// K5: attn2 mean-over-heads + argmax (R3-identical).
// ---------------------------------------------------------------------------
#define MCH 7
__global__ __launch_bounds__(256)
void attn2_kernel(const int* __restrict__ idxs) {
    int b = blockIdx.x / 28;
    int m0 = (blockIdx.x % 28) * MCH;
    __shared__ float qsh[MCH * C_];
    __shared__ float krow[C_];
    __shared__ int sIdxs[NT_];
    int tid = threadIdx.x;
    for (int i = tid; i < MCH * C_; i += 256)
        qsh[i] = G_QC2[((size_t)b * NT_ + m0) * C_ + i];
    for (int i = tid; i < NT_; i += 256) sIdxs[i] = idxs[i];
    int warp = tid >> 5, lane = tid & 31;
    float best = -1e30f;
    int bestn = 0;
    __syncthreads();
    for (int n = 0; n < NT_; n++) {
        __syncthreads();
        for (int i = tid; i < C_; i += 256)
            krow[i] = G_KV[((size_t)b * N_ + sIdxs[n]) * (2 * C_) + i];
        __syncthreads();
        if (warp < MCH) {
            const float* qm = qsh + warp * C_;
            float p = 0.f;
#pragma unroll
            for (int j = 0; j < 12; j++) p += qm[lane + 32 * j] * krow[lane + 32 * j];
#pragma unroll
            for (int o = 16; o; o >>= 1) p += __shfl_xor_sync(0xffffffffu, p, o);
            if (p > best) { best = p; bestn = n; }
        }
    }
    if (warp < MCH && lane == 0)
        G_CENT[(size_t)b * NT_ + m0 + warp] = sIdxs[bestn];
}

// ---------------------------------------------------------------------------
// K6: masked attn3 (sparse over deduped adjusted-index set). (R3-identical.)
// ---------------------------------------------------------------------------
__global__ __launch_bounds__(256)
void attn3_kernel() {
    int bm = blockIdx.x;
    int b = bm / NT_;
    __shared__ unsigned int bmap[N_ / 32];
    __shared__ int sIdx[169];
    __shared__ int cnt;
    __shared__ float sQ[C_];
    __shared__ float sS[H_][169];
    int tid = threadIdx.x;
    if (tid < N_ / 32) bmap[tid] = 0u;
    if (tid == 0) cnt = 0;
    __syncthreads();
    int ci = G_CENT[bm];
    if (tid < 169) {
        int row = tid / 13 - 6;
        int col = tid % 13 - 6;
        int adj = ci + (col - 56 * row);
        adj = max(0, min(N_ - 1, adj));
        atomicOr(&bmap[adj >> 5], 1u << (adj & 31));
    }
    for (int i = tid; i < C_; i += 256)
        sQ[i] = G_QC2[(size_t)bm * C_ + i] * SCALE_;
    __syncthreads();
    if (tid < N_ / 32) {
        unsigned int w = bmap[tid];
        if (w) {
            int base = atomicAdd(&cnt, __popc(w));
            int off = 0;
            while (w) {
                int bit = __ffs(w) - 1;
                w &= w - 1;
                sIdx[base + off] = (tid << 5) + bit;
                off++;
            }
        }
    }
    __syncthreads();
    int count = cnt;
    int h = tid >> 5, lane = tid & 31;
    const float* qh = sQ + h * HD_;
    float mx = -1e30f;
    for (int e = 0; e < count; e++) {
        const float* kr = G_KV + ((size_t)b * N_ + sIdx[e]) * (2 * C_) + h * HD_;
        float p = kr[lane] * qh[lane];
        if (lane < 16) p += kr[lane + 32] * qh[lane + 32];
#pragma unroll
        for (int o = 16; o; o >>= 1) p += __shfl_xor_sync(0xffffffffu, p, o);
        if (lane == 0) sS[h][e] = p;
        mx = fmaxf(mx, p);
    }
    __syncwarp();
    float sum = 0.f;
    for (int e = lane; e < count; e += 32) {
        float ee = expf(sS[h][e] - mx);
        sS[h][e] = ee;
        sum += ee;
    }
#pragma unroll
    for (int o = 16; o; o >>= 1) sum += __shfl_xor_sync(0xffffffffu, sum, o);
    float inv = 1.0f / sum;
    __syncwarp();
    float a0 = 0.f, a1 = 0.f;
    for (int e = 0; e < count; e++) {
        float wgt = sS[h][e];
        const float* vr = G_KV + ((size_t)b * N_ + sIdx[e]) * (2 * C_) + C_ + h * HD_;
        a0 += wgt * vr[lane];
        if (lane < 16) a1 += wgt * vr[lane + 32];
    }
    float* orow = G_AV + (size_t)bm * C_ + h * HD_;
    orow[lane] = a0 * inv;
    if (lane < 16) orow[lane + 32] = a1 * inv;
}

// ---------------------------------------------------------------------------
// Launch: kernel launches only.
// ---------------------------------------------------------------------------
extern "C" void kernel_launch(void* const* d_in, const int* in_sizes, int n_in,
                              void* d_out, int out_size) {
    const float* x      = (const float*)d_in[0];
    const float* q      = (const float*)d_in[1];
    const float* kv_w   = (const float*)d_in[2];
    const float* proj_w = (const float*)d_in[3];
    const float* proj_b = (const float*)d_in[4];
    const float* ln_w   = (const float*)d_in[5];
    const float* ln_b   = (const float*)d_in[6];
    const float* fc1_w  = (const float*)d_in[7];
    const float* fc1_b  = (const float*)d_in[8];
    const float* fc2_w  = (const float*)d_in[9];
    const float* fc2_b  = (const float*)d_in[10];
    const int* idx_sub  = (const int*)d_in[11];
    const int* idxs     = (const int*)d_in[12];
    float* out = (float*)d_out;

    cudaFuncSetAttribute(attn1_kernel,
                         cudaFuncAttributeMaxDynamicSharedMemorySize, ATTN1_SMEM);

    // K0: LayerNorm -> G_XN
    ln_kernel<<<B_ * N_, 128>>>(x, ln_w, ln_b);

    // K1: KV projection (dominant GEMM, fp32-exact)
    {
        dim3 g(2 * C_ / BN, (B_ * N_) / BM);
        gemm_xn_kv<<<g, 256>>>(kv_w);
    }

    // K2: attn1 -> G_QC1
    attn1_kernel<<<B_ * H_, 256, ATTN1_SMEM>>>(q, idx_sub);

    // K3: fc1 + gelu -> G_HB
    {
        dim3 g(2 * C_ / BN, (B_ * NT_) / BM);
        gemm_qc1_hb<<<g, 256>>>(fc1_w, fc1_b);
    }
    // K4: fc2 -> G_QC2
    {
        dim3 g(C_ / BN, (B_ * NT_) / BM);
        gemm_hb_qc2<<<g, 256>>>(fc2_w, fc2_b);
    }

    // K5: attn2 + argmax -> G_CENT
    attn2_kernel<<<B_ * 28, 256>>>(idxs);

    // K6: sparse masked attn3 -> G_AV
    attn3_kernel<<<B_ * NT_, 256>>>();

    // K7: output projection -> d_out
    {
        dim3 g(C_ / BN, (B_ * NT_) / BM);
        gemm_av_out<<<g, 256>>>(proj_w, proj_b, out);
    }
}

// round 14
// speedup vs baseline: 1.1772x; 1.1772x over previous
#include <cuda_runtime.h>
#include <cstdint>
#include <math.h>

#define B_   32
#define N_   3136
#define C_   384
#define H_   8
#define HD_  48
#define NT_  196
#define EPS_ 1e-6f
#define SCALE_ 0.14433756729740643f   /* 1/sqrt(48) */

typedef unsigned long long ull;

// ---------------------------------------------------------------------------
// Scratch: one big static device buffer (R12-identical; no runtime alloc).
// ---------------------------------------------------------------------------
#define XN_OFF   ((size_t)0)
#define KV_OFF   (XN_OFF  + (size_t)B_*N_*C_)
#define QC1_OFF  (KV_OFF  + (size_t)B_*N_*2*C_)
#define HB_OFF   (QC1_OFF + (size_t)B_*NT_*C_)
#define QC2_OFF  (HB_OFF  + (size_t)B_*NT_*2*C_)
#define AV_OFF   (QC2_OFF + (size_t)B_*NT_*C_)
#define CENT_OFF (AV_OFF  + (size_t)B_*NT_*C_)
#define TOTAL_F  (CENT_OFF + (size_t)B_*NT_)

__device__ __align__(128) float g_scratch[TOTAL_F];

#define G_XN   (g_scratch + XN_OFF)
#define G_KV   (g_scratch + KV_OFF)
#define G_QC1  (g_scratch + QC1_OFF)
#define G_HB   (g_scratch + HB_OFF)
#define G_QC2  (g_scratch + QC2_OFF)
#define G_AV   (g_scratch + AV_OFF)
#define G_CENT ((int*)(g_scratch + CENT_OFF))

// ---------------------------------------------------------------------------
// Helpers
// ---------------------------------------------------------------------------
__device__ __forceinline__ float gelu_f(float x) {
    return 0.5f * x * (1.0f + erff(x * 0.70710678118654752f));
}
__device__ __forceinline__ float tf32_hi(float x) {
    uint32_t r;
    asm("cvt.rna.tf32.f32 %0, %1;" : "=r"(r) : "f"(x));
    return __uint_as_float(r);
}

// m16n8k8 tf32 MMA, fp32 accumulate (validated on-device in R5).
__device__ __forceinline__ void mma8(float* d, const uint4& a, const uint2& b) {
    asm volatile(
        "mma.sync.aligned.m16n8k8.row.col.f32.tf32.tf32.f32 "
        "{%0,%1,%2,%3},{%4,%5,%6,%7},{%8,%9},{%0,%1,%2,%3};"
        : "+f"(d[0]), "+f"(d[1]), "+f"(d[2]), "+f"(d[3])
        : "r"(a.x), "r"(a.y), "r"(a.z), "r"(a.w), "r"(b.x), "r"(b.y));
}

// ---------------------------------------------------------------------------
// 3xTF32 GEMM: C[M,Nn] = A[M,K] @ W[Nn,K]^T (+bias)(+gelu)
// Block 128x64, 8 warps (4m x 2n) of 32x32, BK=16.
// On-the-fly hi/lo split (cvt + sub), conflict-free XOR-swizzled smem:
//   idx(p, q=2s+kh, kq, col) = ((p*4+q)*4+kq)*128 + col,
//   col = row ^ (8*(kq ^ q)); verified 1-wavefront STS.32 and LDS.32.
// Register-prefetch single-buffer smem (24 KB static).
// ---------------------------------------------------------------------------
#define BM 128
#define BN 64
#define BK 16

__device__ __forceinline__
void gemm_body(const float* __restrict__ A, const float* __restrict__ W,
               const float* __restrict__ bias, float* __restrict__ Cm,
               int M, int Nn, int K, int epi) {
    __shared__ float sA[4096];
    __shared__ float sB[4096];
    const int tid = threadIdx.x;
    const int lane = tid & 31, warp = tid >> 5;
    const int laneK = lane & 3, laneG = lane >> 2;
    const int mw = (warp & 3) * 32, nw = (warp >> 2) * 32;
    const int m0 = blockIdx.y * BM, n0 = blockIdx.x * BN;

    // Staging: rows rA & rA+64 for A, row rA for B; 4 threads per row.
    const int rA = tid >> 2;
    const int q  = tid & 3;            // = 2s + kh for this thread's float4
    const int cA = q * 4;              // k-offset within chunk
    const float* Ap0 = A + (size_t)(m0 + rA) * K + cA;
    const float* Ap1 = Ap0 + (size_t)64 * K;
    const float* Wp  = W + (size_t)(n0 + rA) * K + cA;

    float acc[2][4][4];
#pragma unroll
    for (int i = 0; i < 2; i++)
#pragma unroll
        for (int j = 0; j < 4; j++)
#pragma unroll
            for (int e = 0; e < 4; e++) acc[i][j][e] = 0.f;

    float4 aR0, aR1, bR;

#define LOADG(cc) do {                                                  \
        aR0 = *(const float4*)(Ap0 + (cc) * BK);                        \
        aR1 = *(const float4*)(Ap1 + (cc) * BK);                        \
        bR  = *(const float4*)(Wp  + (cc) * BK);                        \
    } while (0)

#define SPLIT_STORE(dst, row, x_, j_) do {                              \
        float _hi = tf32_hi(x_);                                        \
        float _lo = (x_) - _hi;                                         \
        int _col = (row) ^ (8 * ((j_) ^ q));                            \
        dst[((0 * 4 + q) * 4 + (j_)) * 128 + _col] = _hi;               \
        dst[((1 * 4 + q) * 4 + (j_)) * 128 + _col] = _lo;               \
    } while (0)

#define STORES() do {                                                   \
        SPLIT_STORE(sA, rA,      aR0.x, 0); SPLIT_STORE(sA, rA,      aR0.y, 1); \
        SPLIT_STORE(sA, rA,      aR0.z, 2); SPLIT_STORE(sA, rA,      aR0.w, 3); \
        SPLIT_STORE(sA, rA + 64, aR1.x, 0); SPLIT_STORE(sA, rA + 64, aR1.y, 1); \
        SPLIT_STORE(sA, rA + 64, aR1.z, 2); SPLIT_STORE(sA, rA + 64, aR1.w, 3); \
        SPLIT_STORE(sB, rA,      bR.x,  0); SPLIT_STORE(sB, rA,      bR.y,  1); \
        SPLIT_STORE(sB, rA,      bR.z,  2); SPLIT_STORE(sB, rA,      bR.w,  3); \
    } while (0)

    int nk = K / BK;
    LOADG(0);
    STORES();
    __syncthreads();

    for (int c = 0; c < nk; c++) {
        if (c + 1 < nk) LOADG(c + 1);
#pragma unroll
        for (int s = 0; s < 2; s++) {
            const int q0 = 2 * s;          // kh = 0
            const int q1 = 2 * s + 1;      // kh = 1
            const int X0 = 8 * (laneK ^ q0);
            const int X1 = 8 * (laneK ^ q1);
            const int aB00 = ((0 * 4 + q0) * 4 + laneK) * 128;  // p=0, kh=0
            const int aB01 = ((0 * 4 + q1) * 4 + laneK) * 128;  // p=0, kh=1
            const int aB10 = ((1 * 4 + q0) * 4 + laneK) * 128;  // p=1, kh=0
            const int aB11 = ((1 * 4 + q1) * 4 + laneK) * 128;  // p=1, kh=1

            uint2 Bh[4], Bl[4];
#pragma unroll
            for (int j = 0; j < 4; j++) {
                int nrow = nw + j * 8 + laneG;
                int c0 = nrow ^ X0, c1 = nrow ^ X1;
                Bh[j].x = __float_as_uint(sB[aB00 + c0]);
                Bh[j].y = __float_as_uint(sB[aB01 + c1]);
                Bl[j].x = __float_as_uint(sB[aB10 + c0]);
                Bl[j].y = __float_as_uint(sB[aB11 + c1]);
            }
#pragma unroll
            for (int i = 0; i < 2; i++) {
                int mr0 = mw + i * 16 + laneG;
                int mr1 = mr0 + 8;
                int c00 = mr0 ^ X0, c10 = mr1 ^ X0;
                int c01 = mr0 ^ X1, c11 = mr1 ^ X1;
                uint4 Ah, Al;
                Ah.x = __float_as_uint(sA[aB00 + c00]);
                Ah.y = __float_as_uint(sA[aB00 + c10]);
                Ah.z = __float_as_uint(sA[aB01 + c01]);
                Ah.w = __float_as_uint(sA[aB01 + c11]);
                Al.x = __float_as_uint(sA[aB10 + c00]);
                Al.y = __float_as_uint(sA[aB10 + c10]);
                Al.z = __float_as_uint(sA[aB11 + c01]);
                Al.w = __float_as_uint(sA[aB11 + c11]);
#pragma unroll
                for (int j = 0; j < 4; j++) {
                    mma8(acc[i][j], Ah, Bh[j]);
                    mma8(acc[i][j], Ah, Bl[j]);
                    mma8(acc[i][j], Al, Bh[j]);
                }
            }
        }
        if (c + 1 < nk) {
            __syncthreads();
            STORES();
            __syncthreads();
        }
    }

    // Epilogue (fragment layout validated in R5)
#pragma unroll
    for (int i = 0; i < 2; i++)
#pragma unroll
        for (int j = 0; j < 4; j++) {
            int r0 = m0 + mw + i * 16 + laneG;
            int c0 = n0 + nw + j * 8 + laneK * 2;
            float d0 = acc[i][j][0], d1 = acc[i][j][1];
            float d2 = acc[i][j][2], d3 = acc[i][j][3];
            if (bias) {
                float b0 = bias[c0], b1 = bias[c0 + 1];
                d0 += b0; d1 += b1; d2 += b0; d3 += b1;
            }
            if (epi == 1) {
                d0 = gelu_f(d0); d1 = gelu_f(d1);
                d2 = gelu_f(d2); d3 = gelu_f(d3);
            }
            float2 w0 = {d0, d1}, w1 = {d2, d3};
            *(float2*)(Cm + (size_t)r0 * Nn + c0) = w0;
            *(float2*)(Cm + (size_t)(r0 + 8) * Nn + c0) = w1;
        }
#undef LOADG
#undef SPLIT_STORE
#undef STORES
}

__global__ __launch_bounds__(256, 2) void gemm_xn_kv(const float* __restrict__ kv_w) {
    gemm_body(G_XN, kv_w, nullptr, G_KV, B_ * N_, 2 * C_, C_, 0);
}
__global__ __launch_bounds__(256, 2) void gemm_qc1_hb(const float* __restrict__ w,
                                                      const float* __restrict__ b) {
    gemm_body(G_QC1, w, b, G_HB, B_ * NT_, 2 * C_, C_, 1);
}
__global__ __launch_bounds__(256, 2) void gemm_hb_qc2(const float* __restrict__ w,
                                                      const float* __restrict__ b) {
    gemm_body(G_HB, w, b, G_QC2, B_ * NT_, C_, 2 * C_, 0);
}
__global__ __launch_bounds__(256, 2) void gemm_av_out(const float* __restrict__ w,
                                                      const float* __restrict__ b,
                                                      float* __restrict__ out) {
    gemm_body(G_AV, w, b, out, B_ * NT_, C_, C_, 0);
}

// ---------------------------------------------------------------------------
// K0: LayerNorm. One block per row, 128 threads. (R12-identical.)
// ---------------------------------------------------------------------------
__global__ void ln_kernel(const float* __restrict__ x,
                          const float* __restrict__ w,
                          const float* __restrict__ b) {
    int row = blockIdx.x;
    const float* xr = x + (size_t)row * C_;
    int tid = threadIdx.x;
    float v[3];
    float s = 0.f, sq = 0.f;
#pragma unroll
    for (int i = 0; i < 3; i++) {
        v[i] = xr[tid + 128 * i];
        s += v[i]; sq += v[i] * v[i];
    }
#pragma unroll
    for (int o = 16; o; o >>= 1) {
        s  += __shfl_xor_sync(0xffffffffu, s, o);
        sq += __shfl_xor_sync(0xffffffffu, sq, o);
    }
    __shared__ float ss[4], ssq[4];
    if ((tid & 31) == 0) { ss[tid >> 5] = s; ssq[tid >> 5] = sq; }
    __syncthreads();
    s  = ss[0] + ss[1] + ss[2] + ss[3];
    sq = ssq[0] + ssq[1] + ssq[2] + ssq[3];
    float mu = s * (1.0f / C_);
    float var = sq * (1.0f / C_) - mu * mu;
    float rstd = rsqrtf(var + EPS_);
    float* orow = G_XN + (size_t)row * C_;
#pragma unroll
    for (int i = 0; i < 3; i++) {
        int c = tid + 128 * i;
        orow[c] = (v[i] - mu) * rstd * w[c] + b[c];
    }
}

// ---------------------------------------------------------------------------
// K2: attn1 + q_cond1. One block per (b,h). (R12-identical.)
// ---------------------------------------------------------------------------
#define ATTN1_SMEM (3 * NT_ * HD_ * 4)

__global__ __launch_bounds__(256)
void attn1_kernel(const float* __restrict__ qg, const int* __restrict__ idx_sub) {
    extern __shared__ float sh[];
    float* qs = sh;
    float* ks = sh + NT_ * HD_;
    float* vs = sh + 2 * NT_ * HD_;
    int b = blockIdx.x >> 3;
    int h = blockIdx.x & 7;
    int tid = threadIdx.x;

    for (int i = tid; i < NT_ * HD_; i += 256) {
        int n = i / HD_, d = i % HD_;
        qs[i] = qg[((size_t)n * H_ + h) * HD_ + d];
        int src = idx_sub[n];
        const float* kvrow = G_KV + ((size_t)b * N_ + src) * (2 * C_) + h * HD_ + d;
        ks[i] = kvrow[0];
        vs[i] = kvrow[C_];
    }
    __syncthreads();

    int m = tid;
    if (m < NT_) {
        float sc[NT_];
        float mx = -1e30f;
        const float* qm = qs + m * HD_;
        for (int n = 0; n < NT_; n++) {
            const float* kn = ks + n * HD_;
            float s = 0.f;
#pragma unroll
            for (int d = 0; d < HD_; d++) s += qm[d] * kn[d];
            s *= SCALE_;
            sc[n] = s;
            mx = fmaxf(mx, s);
        }
        float sum = 0.f;
        for (int n = 0; n < NT_; n++) {
            float e = expf(sc[n] - mx);
            sc[n] = e; sum += e;
        }
        float inv = 1.0f / sum;
        float accv[HD_];
#pragma unroll
        for (int d = 0; d < HD_; d++) accv[d] = 0.f;
        for (int n = 0; n < NT_; n++) {
            float wgt = sc[n];
            const float* vn = vs + n * HD_;
#pragma unroll
            for (int d = 0; d < HD_; d++) accv[d] += wgt * vn[d];
        }
        float* orow = G_QC1 + ((size_t)b * NT_ + m) * C_ + h * HD_;
#pragma unroll
        for (int d = 0; d < HD_; d++) orow[d] = accv[d] * inv;
    }
}

// ---------------------------------------------------------------------------
// K5: attn2 mean-over-heads + argmax (R12-identical).
// ---------------------------------------------------------------------------
#define MCH 7
__global__ __launch_bounds__(256)
void attn2_kernel(const int* __restrict__ idxs) {
    int b = blockIdx.x / 28;
    int m0 = (blockIdx.x % 28) * MCH;
    __shared__ float qsh[MCH * C_];
    __shared__ float krow[C_];
    __shared__ int sIdxs[NT_];
    int tid = threadIdx.x;
    for (int i = tid; i < MCH * C_; i += 256)
        qsh[i] = G_QC2[((size_t)b * NT_ + m0) * C_ + i];
    for (int i = tid; i < NT_; i += 256) sIdxs[i] = idxs[i];
    int warp = tid >> 5, lane = tid & 31;
    float best = -1e30f;
    int bestn = 0;
    __syncthreads();
    for (int n = 0; n < NT_; n++) {
        __syncthreads();
        for (int i = tid; i < C_; i += 256)
            krow[i] = G_KV[((size_t)b * N_ + sIdxs[n]) * (2 * C_) + i];
        __syncthreads();
        if (warp < MCH) {
            const float* qm = qsh + warp * C_;
            float p = 0.f;
#pragma unroll
            for (int j = 0; j < 12; j++) p += qm[lane + 32 * j] * krow[lane + 32 * j];
#pragma unroll
            for (int o = 16; o; o >>= 1) p += __shfl_xor_sync(0xffffffffu, p, o);
            if (p > best) { best = p; bestn = n; }
        }
    }
    if (warp < MCH && lane == 0)
        G_CENT[(size_t)b * NT_ + m0 + warp] = sIdxs[bestn];
}

// ---------------------------------------------------------------------------
// K6: masked attn3 (sparse over deduped adjusted-index set). (R12-identical.)
// ---------------------------------------------------------------------------
__global__ __launch_bounds__(256)
void attn3_kernel() {
    int bm = blockIdx.x;
    int b = bm / NT_;
    __shared__ unsigned int bmap[N_ / 32];
    __shared__ int sIdx[169];
    __shared__ int cnt;
    __shared__ float sQ[C_];
    __shared__ float sS[H_][169];
    int tid = threadIdx.x;
    if (tid < N_ / 32) bmap[tid] = 0u;
    if (tid == 0) cnt = 0;
    __syncthreads();
    int ci = G_CENT[bm];
    if (tid < 169) {
        int row = tid / 13 - 6;
        int col = tid % 13 - 6;
        int adj = ci + (col - 56 * row);
        adj = max(0, min(N_ - 1, adj));
        atomicOr(&bmap[adj >> 5], 1u << (adj & 31));
    }
    for (int i = tid; i < C_; i += 256)
        sQ[i] = G_QC2[(size_t)bm * C_ + i] * SCALE_;
    __syncthreads();
    if (tid < N_ / 32) {
        unsigned int w = bmap[tid];
        if (w) {
            int base = atomicAdd(&cnt, __popc(w));
            int off = 0;
            while (w) {
                int bit = __ffs(w) - 1;
                w &= w - 1;
                sIdx[base + off] = (tid << 5) + bit;
                off++;
            }
        }
    }
    __syncthreads();
    int count = cnt;
    int h = tid >> 5, lane = tid & 31;
    const float* qh = sQ + h * HD_;
    float mx = -1e30f;
    for (int e = 0; e < count; e++) {
        const float* kr = G_KV + ((size_t)b * N_ + sIdx[e]) * (2 * C_) + h * HD_;
        float p = kr[lane] * qh[lane];
        if (lane < 16) p += kr[lane + 32] * qh[lane + 32];
#pragma unroll
        for (int o = 16; o; o >>= 1) p += __shfl_xor_sync(0xffffffffu, p, o);
        if (lane == 0) sS[h][e] = p;
        mx = fmaxf(mx, p);
    }
    __syncwarp();
    float sum = 0.f;
    for (int e = lane; e < count; e += 32) {
        float ee = expf(sS[h][e] - mx);
        sS[h][e] = ee;
        sum += ee;
    }
#pragma unroll
    for (int o = 16; o; o >>= 1) sum += __shfl_xor_sync(0xffffffffu, sum, o);
    float inv = 1.0f / sum;
    __syncwarp();
    float a0 = 0.f, a1 = 0.f;
    for (int e = 0; e < count; e++) {
        float wgt = sS[h][e];
        const float* vr = G_KV + ((size_t)b * N_ + sIdx[e]) * (2 * C_) + C_ + h * HD_;
        a0 += wgt * vr[lane];
        if (lane < 16) a1 += wgt * vr[lane + 32];
    }
    float* orow = G_AV + (size_t)bm * C_ + h * HD_;
    orow[lane] = a0 * inv;
    if (lane < 16) orow[lane + 32] = a1 * inv;
}

// ---------------------------------------------------------------------------
// Launch: kernel launches only.
// ---------------------------------------------------------------------------
extern "C" void kernel_launch(void* const* d_in, const int* in_sizes, int n_in,
                              void* d_out, int out_size) {
    const float* x      = (const float*)d_in[0];
    const float* q      = (const float*)d_in[1];
    const float* kv_w   = (const float*)d_in[2];
    const float* proj_w = (const float*)d_in[3];
    const float* proj_b = (const float*)d_in[4];
    const float* ln_w   = (const float*)d_in[5];
    const float* ln_b   = (const float*)d_in[6];
    const float* fc1_w  = (const float*)d_in[7];
    const float* fc1_b  = (const float*)d_in[8];
    const float* fc2_w  = (const float*)d_in[9];
    const float* fc2_b  = (const float*)d_in[10];
    const int* idx_sub  = (const int*)d_in[11];
    const int* idxs     = (const int*)d_in[12];
    float* out = (float*)d_out;

    cudaFuncSetAttribute(attn1_kernel,
                         cudaFuncAttributeMaxDynamicSharedMemorySize, ATTN1_SMEM);

    // K0: LayerNorm -> G_XN
    ln_kernel<<<B_ * N_, 128>>>(x, ln_w, ln_b);

    // K1: KV projection (3xTF32 tensor-core) -> G_KV
    {
        dim3 g(2 * C_ / BN, (B_ * N_) / BM);
        gemm_xn_kv<<<g, 256>>>(kv_w);
    }

    // K2: attn1 -> G_QC1
    attn1_kernel<<<B_ * H_, 256, ATTN1_SMEM>>>(q, idx_sub);

    // K3: fc1 + gelu -> G_HB
    {
        dim3 g(2 * C_ / BN, (B_ * NT_) / BM);
        gemm_qc1_hb<<<g, 256>>>(fc1_w, fc1_b);
    }
    // K4: fc2 -> G_QC2
    {
        dim3 g(C_ / BN, (B_ * NT_) / BM);
        gemm_hb_qc2<<<g, 256>>>(fc2_w, fc2_b);
    }

    // K5: attn2 + argmax -> G_CENT
    attn2_kernel<<<B_ * 28, 256>>>(idxs);

    // K6: sparse masked attn3 -> G_AV
    attn3_kernel<<<B_ * NT_, 256>>>();

    // K7: output projection -> d_out
    {
        dim3 g(C_ / BN, (B_ * NT_) / BM);
        gemm_av_out<<<g, 256>>>(proj_w, proj_b, out);
    }
}